// round 1
// baseline (speedup 1.0000x reference)
#include <cuda_runtime.h>
#include <cuda_bf16.h>

// Problem constants (from reference):
//   USER_NUM=1000, SKILL_NUM=256, K_HIDDEN=128, N_ITEMS=4096, SEQ_LEN=8192
// out[l, k] = sum_{s : Q[items[l], s] != 0} E[user, s, k]    (Q entries are 0.0/1.0)

#define SEQ_LEN   8192
#define N_ITEMS   4096
#define SKILLS    256
#define K_HIDDEN  128
#define WARPS_PER_CTA 8
#define MAX_NNZ   80   // binomial(256, 0.1): mean 25.6, std 4.8 -> 80 is ~11 sigma

__global__ void __launch_bounds__(WARPS_PER_CTA * 32)
item_emb_sparse_kernel(const int* __restrict__ user_p,
                       const float* __restrict__ Q,        // [N_ITEMS, SKILLS]
                       const int* __restrict__ items,      // [SEQ_LEN]
                       const float* __restrict__ emb,      // [USER_NUM, SKILLS, K_HIDDEN]
                       float* __restrict__ out)            // [SEQ_LEN, K_HIDDEN]
{
    __shared__ int sidx[WARPS_PER_CTA][MAX_NNZ];

    const int tid  = threadIdx.x;
    const int w    = tid >> 5;
    const int lane = tid & 31;
    const int pos  = blockIdx.x * WARPS_PER_CTA + w;   // grid sized exactly: SEQ_LEN/WARPS_PER_CTA
    if (pos >= SEQ_LEN) return;

    // E row base for the selected user (user value is small; first 4 bytes work for i32/i64)
    const int user = user_p[0];
    const float4* __restrict__ E4 =
        reinterpret_cast<const float4*>(emb + (long long)user * SKILLS * K_HIDDEN);

    const int item = items[pos];                       // warp-uniform broadcast load
    const float4* __restrict__ q4 =
        reinterpret_cast<const float4*>(Q + (long long)item * SKILLS);

    // ---- Load Q row: 8 floats per lane (2 x float4), coalesced ----
    const float4 v0 = q4[lane];        // skills 4*lane .. 4*lane+3
    const float4 v1 = q4[lane + 32];   // skills 128+4*lane .. 128+4*lane+3

    // ---- Ballot-compact nonzero skill indices into smem (order irrelevant: we sum) ----
    float vals[8] = {v0.x, v0.y, v0.z, v0.w, v1.x, v1.y, v1.z, v1.w};
    int   svls[8] = {4*lane, 4*lane+1, 4*lane+2, 4*lane+3,
                     128+4*lane, 128+4*lane+1, 128+4*lane+2, 128+4*lane+3};
    const unsigned lt_mask = (1u << lane) - 1u;
    int base = 0;
    #pragma unroll
    for (int t = 0; t < 8; t++) {
        const bool nz = (vals[t] != 0.0f);
        const unsigned m = __ballot_sync(0xffffffffu, nz);
        if (nz) {
            const int p = base + __popc(m & lt_mask);
            if (p < MAX_NNZ) sidx[w][p] = svls[t];
        }
        base += __popc(m);
    }
    __syncwarp();
    const int nnz = min(base, MAX_NNZ);

    // ---- Accumulate: lane owns k = 4*lane .. 4*lane+3 (one float4 of the E row) ----
    float4 acc = make_float4(0.f, 0.f, 0.f, 0.f);
    int j = 0;
    for (; j + 4 <= nnz; j += 4) {
        const int s0 = sidx[w][j + 0];
        const int s1 = sidx[w][j + 1];
        const int s2 = sidx[w][j + 2];
        const int s3 = sidx[w][j + 3];
        const float4 e0 = E4[s0 * (K_HIDDEN / 4) + lane];
        const float4 e1 = E4[s1 * (K_HIDDEN / 4) + lane];
        const float4 e2 = E4[s2 * (K_HIDDEN / 4) + lane];
        const float4 e3 = E4[s3 * (K_HIDDEN / 4) + lane];
        acc.x += (e0.x + e1.x) + (e2.x + e3.x);
        acc.y += (e0.y + e1.y) + (e2.y + e3.y);
        acc.z += (e0.z + e1.z) + (e2.z + e3.z);
        acc.w += (e0.w + e1.w) + (e2.w + e3.w);
    }
    for (; j < nnz; j++) {
        const int s = sidx[w][j];
        const float4 e = E4[s * (K_HIDDEN / 4) + lane];
        acc.x += e.x; acc.y += e.y; acc.z += e.z; acc.w += e.w;
    }

    // ---- Write: every output element covered exactly once ----
    reinterpret_cast<float4*>(out)[pos * (K_HIDDEN / 4) + lane] = acc;
}

extern "C" void kernel_launch(void* const* d_in, const int* in_sizes, int n_in,
                              void* d_out, int out_size)
{
    // Robust input mapping by element count (metadata order should be
    // user, Q_matrix, items, skill_embedding, but match by size to be safe).
    const int*   user  = nullptr;
    const float* Q     = nullptr;
    const int*   items = nullptr;
    const float* emb   = nullptr;

    for (int i = 0; i < n_in; i++) {
        switch (in_sizes[i]) {
            case 1:                      user  = (const int*)  d_in[i]; break;
            case N_ITEMS * SKILLS:       Q     = (const float*)d_in[i]; break;  // 1048576
            case SEQ_LEN:                items = (const int*)  d_in[i]; break;  // 8192
            case 1000 * SKILLS * K_HIDDEN: emb = (const float*)d_in[i]; break;  // 32768000
            default: break;
        }
    }
    // Positional fallback
    if (!user)  user  = (const int*)  d_in[0];
    if (!Q)     Q     = (const float*)d_in[1];
    if (!items) items = (const int*)  d_in[2];
    if (!emb)   emb   = (const float*)d_in[3];

    float* out = (float*)d_out;

    const int threads = WARPS_PER_CTA * 32;
    const int blocks  = SEQ_LEN / WARPS_PER_CTA;   // 1024
    item_emb_sparse_kernel<<<blocks, threads>>>(user, Q, items, emb, out);
}

// round 3
// speedup vs baseline: 1.1368x; 1.1368x over previous
#include <cuda_runtime.h>
#include <cuda_bf16.h>

// USER_NUM=1000, SKILL_NUM=256, K_HIDDEN=128, N_ITEMS=4096, SEQ_LEN=8192
// out[l, k] = sum_{s : Q[items[l], s] != 0} E[user, s, k]
//
// Two-phase: items repeat (8192 positions over 4096 items), so compute
//   R[item] = Q[item] @ E   once per item (phase A, sparse gather-sum)
//   out[l]  = R[items[l]]   (phase B, coalesced gather-copy, L2-resident)

#define SEQ_LEN   8192
#define N_ITEMS   4096
#define SKILLS    256
#define K_HIDDEN  128
#define WARPS_PER_CTA 8
#define MAX_NNZ   96   // binomial(256, 0.1): mean 25.6, std 4.8

// Per-item intermediate: 4096 x 128 floats = 2 MB (static device global; no alloc)
__device__ float4 d_R[N_ITEMS * (K_HIDDEN / 4)];

// ---------------- Phase A: per-item sparse row-sum ----------------
__global__ void __launch_bounds__(WARPS_PER_CTA * 32)
phaseA_item_rowsum(const int* __restrict__ user_p,
                   const float* __restrict__ Q,     // [N_ITEMS, SKILLS]
                   const float* __restrict__ emb)   // [USER_NUM, SKILLS, K_HIDDEN]
{
    __shared__ int sidx[WARPS_PER_CTA][MAX_NNZ];

    const int tid  = threadIdx.x;
    const int w    = tid >> 5;
    const int lane = tid & 31;
    const int item = blockIdx.x * WARPS_PER_CTA + w;   // grid = N_ITEMS/WARPS_PER_CTA

    const int user = user_p[0];
    const float4* __restrict__ E4 =
        reinterpret_cast<const float4*>(emb + (long long)user * SKILLS * K_HIDDEN);

    const float4* __restrict__ q4 =
        reinterpret_cast<const float4*>(Q + (long long)item * SKILLS);

    // Load Q row: 8 floats/lane, coalesced
    const float4 v0 = q4[lane];
    const float4 v1 = q4[lane + 32];

    // Ballot-compact nonzero skill indices (order irrelevant: summation)
    float vals[8] = {v0.x, v0.y, v0.z, v0.w, v1.x, v1.y, v1.z, v1.w};
    int   svls[8] = {4*lane, 4*lane+1, 4*lane+2, 4*lane+3,
                     128+4*lane, 128+4*lane+1, 128+4*lane+2, 128+4*lane+3};
    const unsigned lt_mask = (1u << lane) - 1u;
    int base = 0;
    #pragma unroll
    for (int t = 0; t < 8; t++) {
        const bool nz = (vals[t] != 0.0f);
        const unsigned m = __ballot_sync(0xffffffffu, nz);
        if (nz) {
            const int p = base + __popc(m & lt_mask);
            if (p < MAX_NNZ) sidx[w][p] = svls[t];
        }
        base += __popc(m);
    }
    __syncwarp();
    const int nnz = min(base, MAX_NNZ);

    // Gather-accumulate, unroll x8 with two independent accumulators (MLP=8)
    float4 a0 = make_float4(0.f, 0.f, 0.f, 0.f);
    float4 a1 = make_float4(0.f, 0.f, 0.f, 0.f);
    int j = 0;
    for (; j + 8 <= nnz; j += 8) {
        const int s0 = sidx[w][j+0], s1 = sidx[w][j+1];
        const int s2 = sidx[w][j+2], s3 = sidx[w][j+3];
        const int s4 = sidx[w][j+4], s5 = sidx[w][j+5];
        const int s6 = sidx[w][j+6], s7 = sidx[w][j+7];
        const float4 e0 = E4[s0 * 32 + lane];
        const float4 e1 = E4[s1 * 32 + lane];
        const float4 e2 = E4[s2 * 32 + lane];
        const float4 e3 = E4[s3 * 32 + lane];
        const float4 e4 = E4[s4 * 32 + lane];
        const float4 e5 = E4[s5 * 32 + lane];
        const float4 e6 = E4[s6 * 32 + lane];
        const float4 e7 = E4[s7 * 32 + lane];
        a0.x += (e0.x + e1.x) + (e2.x + e3.x);
        a0.y += (e0.y + e1.y) + (e2.y + e3.y);
        a0.z += (e0.z + e1.z) + (e2.z + e3.z);
        a0.w += (e0.w + e1.w) + (e2.w + e3.w);
        a1.x += (e4.x + e5.x) + (e6.x + e7.x);
        a1.y += (e4.y + e5.y) + (e6.y + e7.y);
        a1.z += (e4.z + e5.z) + (e6.z + e7.z);
        a1.w += (e4.w + e5.w) + (e6.w + e7.w);
    }
    for (; j + 4 <= nnz; j += 4) {
        const int s0 = sidx[w][j+0], s1 = sidx[w][j+1];
        const int s2 = sidx[w][j+2], s3 = sidx[w][j+3];
        const float4 e0 = E4[s0 * 32 + lane];
        const float4 e1 = E4[s1 * 32 + lane];
        const float4 e2 = E4[s2 * 32 + lane];
        const float4 e3 = E4[s3 * 32 + lane];
        a0.x += (e0.x + e1.x) + (e2.x + e3.x);
        a0.y += (e0.y + e1.y) + (e2.y + e3.y);
        a0.z += (e0.z + e1.z) + (e2.z + e3.z);
        a0.w += (e0.w + e1.w) + (e2.w + e3.w);
    }
    for (; j < nnz; j++) {
        const int s = sidx[w][j];
        const float4 e = E4[s * 32 + lane];
        a1.x += e.x; a1.y += e.y; a1.z += e.z; a1.w += e.w;
    }

    float4 acc;
    acc.x = a0.x + a1.x; acc.y = a0.y + a1.y;
    acc.z = a0.z + a1.z; acc.w = a0.w + a1.w;
    d_R[item * 32 + lane] = acc;
}

// ---------------- Phase B: gather-copy out[l] = R[items[l]] ----------------
__global__ void __launch_bounds__(256)
phaseB_gather(const int* __restrict__ items,   // [SEQ_LEN]
              float4* __restrict__ out4)       // [SEQ_LEN * 32] float4
{
    const int idx  = blockIdx.x * blockDim.x + threadIdx.x;  // 0 .. SEQ_LEN*32-1
    const int pos  = idx >> 5;
    const int q    = idx & 31;
    const int item = __ldg(&items[pos]);       // broadcast within each 32-thread group
    out4[idx] = d_R[item * 32 + q];
}

extern "C" void kernel_launch(void* const* d_in, const int* in_sizes, int n_in,
                              void* d_out, int out_size)
{
    const int*   user  = nullptr;
    const float* Q     = nullptr;
    const int*   items = nullptr;
    const float* emb   = nullptr;

    for (int i = 0; i < n_in; i++) {
        switch (in_sizes[i]) {
            case 1:                        user  = (const int*)  d_in[i]; break;
            case N_ITEMS * SKILLS:         Q     = (const float*)d_in[i]; break;
            case SEQ_LEN:                  items = (const int*)  d_in[i]; break;
            case 1000 * SKILLS * K_HIDDEN: emb   = (const float*)d_in[i]; break;
            default: break;
        }
    }
    if (!user)  user  = (const int*)  d_in[0];
    if (!Q)     Q     = (const float*)d_in[1];
    if (!items) items = (const int*)  d_in[2];
    if (!emb)   emb   = (const float*)d_in[3];

    // Phase A: one warp per item
    phaseA_item_rowsum<<<N_ITEMS / WARPS_PER_CTA, WARPS_PER_CTA * 32>>>(user, Q, emb);

    // Phase B: one thread per output float4
    const int totalB = SEQ_LEN * (K_HIDDEN / 4);   // 262144
    phaseB_gather<<<totalB / 256, 256>>>(items, (float4*)d_out);
}

// round 4
// speedup vs baseline: 1.1633x; 1.0233x over previous
#include <cuda_runtime.h>
#include <cuda_bf16.h>

// USER_NUM=1000, SKILL_NUM=256, K_HIDDEN=128, N_ITEMS=4096, SEQ_LEN=8192
// out[l, k] = sum_{s : Q[items[l], s] != 0} E[user, s, k]
//
// Two-phase: items repeat (8192 positions over 4096 items):
//   R[item] = Q[item] @ E   (phase A: sparse gather-sum, one warp/item, MLP=12)
//   out[l]  = R[items[l]]   (phase B: gather-copy, 4 positions per thread, MLP=4)

#define SEQ_LEN   8192
#define N_ITEMS   4096
#define SKILLS    256
#define K_HIDDEN  128
#define MAX_NNZ   96   // binomial(256, 0.1): mean 25.6, std 4.8

#define A_WARPS_PER_CTA 4            // 128-thread CTAs -> 1024 CTAs
#define B_THREADS 256
#define B_ITEMS_PER_THREAD 4

// Per-item intermediate: 4096 x 128 floats = 2 MB (static device global; no alloc)
__device__ float4 d_R[N_ITEMS * (K_HIDDEN / 4)];

// ---------------- Phase A: per-item sparse row-sum ----------------
__global__ void __launch_bounds__(A_WARPS_PER_CTA * 32)
phaseA_item_rowsum(const int* __restrict__ user_p,
                   const float* __restrict__ Q,     // [N_ITEMS, SKILLS]
                   const float* __restrict__ emb)   // [USER_NUM, SKILLS, K_HIDDEN]
{
    __shared__ int sidx[A_WARPS_PER_CTA][MAX_NNZ];

    const int tid  = threadIdx.x;
    const int w    = tid >> 5;
    const int lane = tid & 31;
    const int item = blockIdx.x * A_WARPS_PER_CTA + w;  // grid = N_ITEMS/A_WARPS_PER_CTA

    const int user = user_p[0];
    const float4* __restrict__ E4 =
        reinterpret_cast<const float4*>(emb + (long long)user * SKILLS * K_HIDDEN);

    const float4* __restrict__ q4 =
        reinterpret_cast<const float4*>(Q + (long long)item * SKILLS);

    // Load Q row: 8 floats/lane, coalesced
    const float4 v0 = q4[lane];
    const float4 v1 = q4[lane + 32];

    // Ballot-compact nonzero skill indices (order irrelevant: summation)
    float vals[8] = {v0.x, v0.y, v0.z, v0.w, v1.x, v1.y, v1.z, v1.w};
    int   svls[8] = {4*lane, 4*lane+1, 4*lane+2, 4*lane+3,
                     128+4*lane, 128+4*lane+1, 128+4*lane+2, 128+4*lane+3};
    const unsigned lt_mask = (1u << lane) - 1u;
    int base = 0;
    #pragma unroll
    for (int t = 0; t < 8; t++) {
        const bool nz = (vals[t] != 0.0f);
        const unsigned m = __ballot_sync(0xffffffffu, nz);
        if (nz) {
            const int p = base + __popc(m & lt_mask);
            if (p < MAX_NNZ) sidx[w][p] = svls[t];
        }
        base += __popc(m);
    }
    __syncwarp();
    const int nnz = min(base, MAX_NNZ);

    // Gather-accumulate: 12 independent loads in flight, 3 accumulators
    float4 a0 = make_float4(0.f, 0.f, 0.f, 0.f);
    float4 a1 = make_float4(0.f, 0.f, 0.f, 0.f);
    float4 a2 = make_float4(0.f, 0.f, 0.f, 0.f);
    int j = 0;
    for (; j + 12 <= nnz; j += 12) {
        int s[12];
        #pragma unroll
        for (int t = 0; t < 12; t++) s[t] = sidx[w][j + t];
        float4 e[12];
        #pragma unroll
        for (int t = 0; t < 12; t++) e[t] = E4[s[t] * 32 + lane];
        #pragma unroll
        for (int t = 0; t < 4; t++) {
            a0.x += e[t].x;     a0.y += e[t].y;     a0.z += e[t].z;     a0.w += e[t].w;
            a1.x += e[t+4].x;   a1.y += e[t+4].y;   a1.z += e[t+4].z;   a1.w += e[t+4].w;
            a2.x += e[t+8].x;   a2.y += e[t+8].y;   a2.z += e[t+8].z;   a2.w += e[t+8].w;
        }
    }
    for (; j + 4 <= nnz; j += 4) {
        const int s0 = sidx[w][j+0], s1 = sidx[w][j+1];
        const int s2 = sidx[w][j+2], s3 = sidx[w][j+3];
        const float4 e0 = E4[s0 * 32 + lane];
        const float4 e1 = E4[s1 * 32 + lane];
        const float4 e2 = E4[s2 * 32 + lane];
        const float4 e3 = E4[s3 * 32 + lane];
        a0.x += (e0.x + e1.x) + (e2.x + e3.x);
        a0.y += (e0.y + e1.y) + (e2.y + e3.y);
        a0.z += (e0.z + e1.z) + (e2.z + e3.z);
        a0.w += (e0.w + e1.w) + (e2.w + e3.w);
    }
    for (; j < nnz; j++) {
        const int s = sidx[w][j];
        const float4 e = E4[s * 32 + lane];
        a1.x += e.x; a1.y += e.y; a1.z += e.z; a1.w += e.w;
    }

    float4 acc;
    acc.x = (a0.x + a1.x) + a2.x;
    acc.y = (a0.y + a1.y) + a2.y;
    acc.z = (a0.z + a1.z) + a2.z;
    acc.w = (a0.w + a1.w) + a2.w;
    d_R[item * 32 + lane] = acc;
}

// ---------------- Phase B: gather-copy out[l] = R[items[l]], MLP=4 ----------------
__global__ void __launch_bounds__(B_THREADS)
phaseB_gather(const int* __restrict__ items,   // [SEQ_LEN]
              float4* __restrict__ out4)       // [SEQ_LEN * 32] float4
{
    // Total float4 elements: SEQ_LEN * 32 = 262144. Each thread handles 4,
    // strided by total thread count so every warp covers whole positions
    // (32 consecutive float4 = one position) -> coalesced loads and stores.
    const int STRIDE = (SEQ_LEN * (K_HIDDEN / 4)) / B_ITEMS_PER_THREAD;  // 65536
    const int t = blockIdx.x * B_THREADS + threadIdx.x;                  // 0..65535

    int g[B_ITEMS_PER_THREAD];
    int it[B_ITEMS_PER_THREAD];
    #pragma unroll
    for (int u = 0; u < B_ITEMS_PER_THREAD; u++) {
        g[u]  = t + u * STRIDE;
        it[u] = __ldg(&items[g[u] >> 5]);      // warp-uniform per u
    }
    float4 r[B_ITEMS_PER_THREAD];
    #pragma unroll
    for (int u = 0; u < B_ITEMS_PER_THREAD; u++)
        r[u] = d_R[it[u] * 32 + (g[u] & 31)];  // 4 independent LDG.128
    #pragma unroll
    for (int u = 0; u < B_ITEMS_PER_THREAD; u++)
        out4[g[u]] = r[u];
}

extern "C" void kernel_launch(void* const* d_in, const int* in_sizes, int n_in,
                              void* d_out, int out_size)
{
    const int*   user  = nullptr;
    const float* Q     = nullptr;
    const int*   items = nullptr;
    const float* emb   = nullptr;

    for (int i = 0; i < n_in; i++) {
        switch (in_sizes[i]) {
            case 1:                        user  = (const int*)  d_in[i]; break;
            case N_ITEMS * SKILLS:         Q     = (const float*)d_in[i]; break;
            case SEQ_LEN:                  items = (const int*)  d_in[i]; break;
            case 1000 * SKILLS * K_HIDDEN: emb   = (const float*)d_in[i]; break;
            default: break;
        }
    }
    if (!user)  user  = (const int*)  d_in[0];
    if (!Q)     Q     = (const float*)d_in[1];
    if (!items) items = (const int*)  d_in[2];
    if (!emb)   emb   = (const float*)d_in[3];

    // Phase A: one warp per item, 128-thread CTAs
    phaseA_item_rowsum<<<N_ITEMS / A_WARPS_PER_CTA, A_WARPS_PER_CTA * 32>>>(user, Q, emb);

    // Phase B: 4 float4s per thread
    const int totalB_threads = (SEQ_LEN * (K_HIDDEN / 4)) / B_ITEMS_PER_THREAD;  // 65536
    phaseB_gather<<<totalB_threads / B_THREADS, B_THREADS>>>(items, (float4*)d_out);
}